// round 16
// baseline (speedup 1.0000x reference)
#include <cuda_runtime.h>
#include <cuda_fp16.h>
#include <math.h>
#include <stdint.h>

#define T_LEN 1024
#define HID   2048
#define NHEAD 32
#define HEADD 64
#define NTOK_EL (T_LEN * HID)
#define NPAIR (T_LEN / 2)

#define ASLOT_H ((size_t)T_LEN * 2 * HID)   // activation slot: [M, 2K] fp16
#define WSLOT_H ((size_t)HID * HID)         // big W slot: [N, K] fp16
#define LSLOT_H ((size_t)128 * HID)         // lora-down W slot (padded 128 rows)
#define USLOT_H ((size_t)HID * 128)         // lora-up W slot: [2048, 128] fp16 padded

// ---------------- static device scratch ----------------
__device__ float g_scratch[8u * (unsigned)NTOK_EL];
__device__ float g_pscan2[(size_t)NPAIR * NHEAD * 1024];
__device__ float g_y[(size_t)T_LEN * HID];
__device__ __align__(256) __half g_abuf[6 * ASLOT_H];
__device__ __align__(256) __half g_wbuf[4 * WSLOT_H];
__device__ __align__(256) __half g_g1buf[(size_t)256 * HID];
__device__ __align__(256) __half g_g2buf[(size_t)HID * 256];
__device__ __align__(256) __half g_ghbuf[(size_t)T_LEN * 256];
__device__ __align__(256) __half g_lorabuf[3 * LSLOT_H];
__device__ __align__(256) __half g_upbuf[3 * USLOT_H];
__device__ __align__(256) __half g_hbuf_h[(size_t)T_LEN * 384];

#define S_R   0
#define S_K   1
#define S_V   2
#define S_K2  3
#define S_G   4
#define S_TMP 5

// ---------------- helpers ----------------
__device__ __forceinline__ float blk_sum256(float v) {
    __shared__ float sh[8];
    int tid = threadIdx.x;
#pragma unroll
    for (int o = 16; o; o >>= 1) v += __shfl_xor_sync(0xffffffffu, v, o);
    if ((tid & 31) == 0) sh[tid >> 5] = v;
    __syncthreads();
    if (tid == 0) {
        float s = 0.f;
#pragma unroll
        for (int i = 0; i < 8; i++) s += sh[i];
        sh[0] = s;
    }
    __syncthreads();
    float r = sh[0];
    __syncthreads();
    return r;
}

__device__ __forceinline__ float warp_sum(float v) {
#pragma unroll
    for (int o = 16; o; o >>= 1) v += __shfl_xor_sync(0xffffffffu, v, o);
    return v;
}

__device__ __forceinline__ float sigmoidf(float v) {
    return 1.f / (1.f + __expf(-v));
}

__device__ __forceinline__ uint32_t smem_u32(const void* p) {
    uint32_t a;
    asm("{ .reg .u64 t; cvta.to.shared.u64 t, %1; cvt.u32.u64 %0, t; }" : "=r"(a) : "l"(p));
    return a;
}

__device__ __forceinline__ void hsplit(float v, __half& hi, __half& lo) {
    hi = __float2half_rn(v);
    lo = __float2half_rn(v - __half2float(hi));
}

// ======================= mma.sync fp16 GEMM =======================
#define MMK_STRIDE 80
#define MMK_TILE   (128 * MMK_STRIDE)
#define STAGE_BYTES (3 * MMK_TILE)
#define MM_SMEM (3 * STAGE_BYTES)

// modes: 0 fp32 store | 1 +Res fp32 | 4 sigmoid->fp16 | 5 fp16 | 6 tanh->fp16
//        7 sigmoid(bias+x)->fp32 | 8 exp(-.606531*sigmoid(bias+x))->fp32
//        9 C = C + (Res-C)*sigmoid(bias+x)  (fp32 rmw)
struct MMJob {
    const __half* A; const __half* B; float* C; const float* Res; const float* bias;
    int N; int K; int lda; int ldc; int mode; int planes;
};
struct MMJobs { MMJob j[7]; };

__device__ __forceinline__ void cp16(uint32_t dst, const void* src) {
    asm volatile("cp.async.cg.shared.global [%0], [%1], 16;" :: "r"(dst), "l"(src));
}

__device__ __forceinline__ void ldsm4(uint32_t* r, uint32_t a) {
    asm volatile("ldmatrix.sync.aligned.m8n8.x4.shared.b16 {%0,%1,%2,%3}, [%4];"
                 : "=r"(r[0]), "=r"(r[1]), "=r"(r[2]), "=r"(r[3]) : "r"(a));
}

__device__ __forceinline__ void mma16816(float* c, const uint32_t* a, const uint32_t* b) {
    asm volatile(
        "mma.sync.aligned.m16n8k16.row.col.f32.f16.f16.f32 "
        "{%0,%1,%2,%3}, {%4,%5,%6,%7}, {%8,%9}, {%0,%1,%2,%3};"
        : "+f"(c[0]), "+f"(c[1]), "+f"(c[2]), "+f"(c[3])
        : "r"(a[0]), "r"(a[1]), "r"(a[2]), "r"(a[3]), "r"(b[0]), "r"(b[1]));
}

__device__ __forceinline__ void mm_epilogue(
    const MMJob& job, int row, int col, float2 v0, float2 v1)
{
    float* C = job.C;
    int ldc = job.ldc;
    int mode = job.mode;
    if (mode == 4 || mode == 5 || mode == 6) {
        __half* Ch = (__half*)C;
        if (mode == 4) {
            v0.x = sigmoidf(v0.x); v0.y = sigmoidf(v0.y);
            v1.x = sigmoidf(v1.x); v1.y = sigmoidf(v1.y);
        } else if (mode == 6) {
            v0.x = tanhf(v0.x); v0.y = tanhf(v0.y);
            v1.x = tanhf(v1.x); v1.y = tanhf(v1.y);
        }
        *(__half2*)(Ch + (size_t)row * ldc + col) = __floats2half2_rn(v0.x, v0.y);
        *(__half2*)(Ch + (size_t)(row + 8) * ldc + col) = __floats2half2_rn(v1.x, v1.y);
        return;
    }
    if (mode == 1) {
        const float2 r0 = *(const float2*)(job.Res + (size_t)row * ldc + col);
        const float2 r1 = *(const float2*)(job.Res + (size_t)(row + 8) * ldc + col);
        v0.x += r0.x; v0.y += r0.y;
        v1.x += r1.x; v1.y += r1.y;
    } else if (mode == 7 || mode == 8 || mode == 9) {
        float b0 = job.bias[col], b1 = job.bias[col + 1];
        float s00 = sigmoidf(b0 + v0.x), s01 = sigmoidf(b1 + v0.y);
        float s10 = sigmoidf(b0 + v1.x), s11 = sigmoidf(b1 + v1.y);
        if (mode == 7) {
            v0 = make_float2(s00, s01); v1 = make_float2(s10, s11);
        } else if (mode == 8) {
            v0 = make_float2(__expf(-0.606531f * s00), __expf(-0.606531f * s01));
            v1 = make_float2(__expf(-0.606531f * s10), __expf(-0.606531f * s11));
        } else {
            float2 c0 = *(const float2*)(C + (size_t)row * ldc + col);
            float2 c1 = *(const float2*)(C + (size_t)(row + 8) * ldc + col);
            const float2 f0 = *(const float2*)(job.Res + (size_t)row * ldc + col);
            const float2 f1 = *(const float2*)(job.Res + (size_t)(row + 8) * ldc + col);
            v0 = make_float2(c0.x + (f0.x - c0.x) * s00, c0.y + (f0.y - c0.y) * s01);
            v1 = make_float2(c1.x + (f1.x - c1.x) * s10, c1.y + (f1.y - c1.y) * s11);
        }
    }
    *(float2*)(C + (size_t)row * ldc + col) = v0;
    *(float2*)(C + (size_t)(row + 8) * ldc + col) = v1;
}

__global__ void __launch_bounds__(256, 2) mm128_kernel(MMJobs jobs, int nz)
{
    extern __shared__ __align__(16) char smem[];
    uint32_t sbase = smem_u32(smem);

    const MMJob job = jobs.j[blockIdx.z];
    const int N = job.N;
    int n0 = blockIdx.x * 128;
    if (n0 >= N) return;
    int m0 = blockIdx.y * 128;

    const __half* Ab = job.A;
    const __half* Bb = job.B;
    const int K = job.K;
    const int lda = job.lda;
    const int nk = K >> 5;
    const int planes = job.planes;

    int tid = threadIdx.x;
    int wid = tid >> 5, lane = tid & 31;
    int g = lane >> 2, tig = lane & 3;
    int warp_m = wid >> 2;
    int warp_n = wid & 3;

    float acc[4][4][4];
#pragma unroll
    for (int i = 0; i < 4; i++)
#pragma unroll
        for (int j = 0; j < 4; j++)
#pragma unroll
            for (int q = 0; q < 4; q++) acc[i][j][q] = 0.f;

    auto load_stage = [&](int s, int kc) {
        uint32_t st = sbase + s * STAGE_BYTES;
        int k0 = kc << 5;
#pragma unroll
        for (int it = 0; it < 2; it++) {
            int idx = tid + it * 256;
            int r = idx >> 2, c = idx & 3;
            cp16(st + r * MMK_STRIDE + c * 16, Ab + ((size_t)(m0 + r) * lda + k0 + c * 8));
        }
        if (planes == 2) {
#pragma unroll
            for (int it = 0; it < 2; it++) {
                int idx = tid + it * 256;
                int r = idx >> 2, c = idx & 3;
                cp16(st + MMK_TILE + r * MMK_STRIDE + c * 16,
                     Ab + ((size_t)(m0 + r) * lda + K + k0 + c * 8));
            }
        }
#pragma unroll
        for (int it = 0; it < 2; it++) {
            int idx = tid + it * 256;
            int r = idx >> 2, c = idx & 3;
            cp16(st + 2 * MMK_TILE + r * MMK_STRIDE + c * 16,
                 Bb + ((size_t)(n0 + r) * K + k0 + c * 8));
        }
        asm volatile("cp.async.commit_group;" ::: "memory");
    };

    load_stage(0, 0);
    if (nk > 1) load_stage(1, 1);
    else asm volatile("cp.async.commit_group;" ::: "memory");

    int aRowSel = (lane & 15);
    int aColSel = (lane & 16) ? 16 : 0;
    int bRowSel = ((lane & 16) ? 8 : 0) + (lane & 7);
    int bColSel = (lane & 8) ? 16 : 0;

    for (int kc = 0; kc < nk; kc++) {
        asm volatile("cp.async.wait_group 1;" ::: "memory");
        __syncthreads();
        if (kc + 2 < nk) load_stage((kc + 2) % 3, kc + 2);
        else asm volatile("cp.async.commit_group;" ::: "memory");

        uint32_t st = sbase + (kc % 3) * STAGE_BYTES;
#pragma unroll
        for (int ks = 0; ks < 2; ks++) {
            uint32_t afr[4][4], bfr[2][4];
#pragma unroll
            for (int ap = 0; ap < 2; ap++) {
                uint32_t addr = st + 2 * MMK_TILE
                                + (uint32_t)(warp_n * 32 + ap * 16 + bRowSel) * MMK_STRIDE
                                + ks * 32 + bColSel;
                ldsm4(bfr[ap], addr);
            }
#pragma unroll
            for (int am = 0; am < 4; am++) {
                uint32_t addr = st + (uint32_t)(warp_m * 64 + am * 16 + aRowSel) * MMK_STRIDE
                                + ks * 32 + aColSel;
                ldsm4(afr[am], addr);
            }
#pragma unroll
            for (int am = 0; am < 4; am++) {
                mma16816(acc[am][0], afr[am], &bfr[0][0]);
                mma16816(acc[am][1], afr[am], &bfr[0][2]);
                mma16816(acc[am][2], afr[am], &bfr[1][0]);
                mma16816(acc[am][3], afr[am], &bfr[1][2]);
            }
            if (planes == 2) {
#pragma unroll
                for (int am = 0; am < 4; am++) {
                    uint32_t addr = st + MMK_TILE
                                    + (uint32_t)(warp_m * 64 + am * 16 + aRowSel) * MMK_STRIDE
                                    + ks * 32 + aColSel;
                    ldsm4(afr[am], addr);
                }
#pragma unroll
                for (int am = 0; am < 4; am++) {
                    mma16816(acc[am][0], afr[am], &bfr[0][0]);
                    mma16816(acc[am][1], afr[am], &bfr[0][2]);
                    mma16816(acc[am][2], afr[am], &bfr[1][0]);
                    mma16816(acc[am][3], afr[am], &bfr[1][2]);
                }
            }
        }
    }

    __syncthreads();

#pragma unroll
    for (int am = 0; am < 4; am++) {
#pragma unroll
        for (int an = 0; an < 4; an++) {
            int row = m0 + warp_m * 64 + am * 16 + g;
            int col = n0 + warp_n * 32 + an * 8 + tig * 2;
            mm_epilogue(job, row, col,
                        make_float2(acc[am][an][0], acc[am][an][1]),
                        make_float2(acc[am][an][2], acc[am][an][3]));
        }
    }
}

// ---------------- mm64: batched 64x128 tile variant ----------------
#define MM64_A_TILE (64 * MMK_STRIDE)
#define MM64_STAGE  (2 * MM64_A_TILE + MMK_TILE)
#define MM64_SMEM   (3 * MM64_STAGE)

__global__ void __launch_bounds__(256, 2) mm64_kernel(MMJobs jobs)
{
    extern __shared__ __align__(16) char smem[];
    uint32_t sbase = smem_u32(smem);

    const MMJob job = jobs.j[blockIdx.z];
    const int N = job.N;
    int n0 = blockIdx.x * 128;
    if (n0 >= N) return;
    int m0 = blockIdx.y * 64;

    const __half* Ab = job.A;
    const __half* Bb = job.B;
    const int K = job.K;
    const int lda = job.lda;
    const int nk = K >> 5;
    const int planes = job.planes;

    int tid = threadIdx.x;
    int wid = tid >> 5, lane = tid & 31;
    int g = lane >> 2, tig = lane & 3;
    int warp_m = wid >> 2;
    int warp_n = wid & 3;

    float acc[2][4][4];
#pragma unroll
    for (int i = 0; i < 2; i++)
#pragma unroll
        for (int j = 0; j < 4; j++)
#pragma unroll
            for (int q = 0; q < 4; q++) acc[i][j][q] = 0.f;

    auto load_stage = [&](int s, int kc) {
        uint32_t st = sbase + s * MM64_STAGE;
        int k0 = kc << 5;
        {
            int r = tid >> 2, c = tid & 3;
            cp16(st + r * MMK_STRIDE + c * 16, Ab + ((size_t)(m0 + r) * lda + k0 + c * 8));
        }
        if (planes == 2) {
            int r = tid >> 2, c = tid & 3;
            cp16(st + MM64_A_TILE + r * MMK_STRIDE + c * 16,
                 Ab + ((size_t)(m0 + r) * lda + K + k0 + c * 8));
        }
#pragma unroll
        for (int it = 0; it < 2; it++) {
            int idx = tid + it * 256;
            int r = idx >> 2, c = idx & 3;
            cp16(st + 2 * MM64_A_TILE + r * MMK_STRIDE + c * 16,
                 Bb + ((size_t)(n0 + r) * K + k0 + c * 8));
        }
        asm volatile("cp.async.commit_group;" ::: "memory");
    };

    load_stage(0, 0);
    if (nk > 1) load_stage(1, 1);
    else asm volatile("cp.async.commit_group;" ::: "memory");

    int aRowSel = (lane & 15);
    int aColSel = (lane & 16) ? 16 : 0;
    int bRowSel = ((lane & 16) ? 8 : 0) + (lane & 7);
    int bColSel = (lane & 8) ? 16 : 0;

    for (int kc = 0; kc < nk; kc++) {
        asm volatile("cp.async.wait_group 1;" ::: "memory");
        __syncthreads();
        if (kc + 2 < nk) load_stage((kc + 2) % 3, kc + 2);
        else asm volatile("cp.async.commit_group;" ::: "memory");

        uint32_t st = sbase + (kc % 3) * MM64_STAGE;
#pragma unroll
        for (int ks = 0; ks < 2; ks++) {
            uint32_t afr[2][4], bfr[2][4];
#pragma unroll
            for (int ap = 0; ap < 2; ap++) {
                uint32_t addr = st + 2 * MM64_A_TILE
                                + (uint32_t)(warp_n * 32 + ap * 16 + bRowSel) * MMK_STRIDE
                                + ks * 32 + bColSel;
                ldsm4(bfr[ap], addr);
            }
#pragma unroll
            for (int am = 0; am < 2; am++) {
                uint32_t addr = st + (uint32_t)(warp_m * 32 + am * 16 + aRowSel) * MMK_STRIDE
                                + ks * 32 + aColSel;
                ldsm4(afr[am], addr);
            }
#pragma unroll
            for (int am = 0; am < 2; am++) {
                mma16816(acc[am][0], afr[am], &bfr[0][0]);
                mma16816(acc[am][1], afr[am], &bfr[0][2]);
                mma16816(acc[am][2], afr[am], &bfr[1][0]);
                mma16816(acc[am][3], afr[am], &bfr[1][2]);
            }
            if (planes == 2) {
#pragma unroll
                for (int am = 0; am < 2; am++) {
                    uint32_t addr = st + MM64_A_TILE
                                    + (uint32_t)(warp_m * 32 + am * 16 + aRowSel) * MMK_STRIDE
                                    + ks * 32 + aColSel;
                    ldsm4(afr[am], addr);
                }
#pragma unroll
                for (int am = 0; am < 2; am++) {
                    mma16816(acc[am][0], afr[am], &bfr[0][0]);
                    mma16816(acc[am][1], afr[am], &bfr[0][2]);
                    mma16816(acc[am][2], afr[am], &bfr[1][0]);
                    mma16816(acc[am][3], afr[am], &bfr[1][2]);
                }
            }
        }
    }

    __syncthreads();

#pragma unroll
    for (int am = 0; am < 2; am++) {
#pragma unroll
        for (int an = 0; an < 4; an++) {
            int row = m0 + warp_m * 32 + am * 16 + g;
            int col = n0 + warp_n * 32 + an * 8 + tig * 2;
            mm_epilogue(job, row, col,
                        make_float2(acc[am][an][0], acc[am][an][1]),
                        make_float2(acc[am][an][2], acc[am][an][3]));
        }
    }
}

// ---------------- front-end: ln_mix + weight conversions + v_first copy ----------------
__device__ __forceinline__ void conv_tile2(const float* __restrict__ W, __half* __restrict__ out,
                                           int K, int N, int bx, int by, float* tile,
                                           int kmax)
{
    int k0 = by * 64, n0 = bx * 32;
    int tid = threadIdx.x;
#pragma unroll
    for (int it = 0; it < 8; it++) {
        int i = tid + it * 256;
        int r = i >> 5, c = i & 31;
        tile[r * 33 + c] = (k0 + r < kmax) ? W[(size_t)(k0 + r) * N + n0 + c] : 0.f;
    }
    __syncthreads();
    int nl = tid >> 3;
    int kq = (tid & 7) * 8;
    __half h8[8];
#pragma unroll
    for (int j = 0; j < 8; j++)
        h8[j] = __float2half_rn(tile[(kq + j) * 33 + nl]);
    *(uint4*)(out + (size_t)(n0 + nl) * K + k0 + kq) = *(uint4*)h8;
}

__device__ void ln_mix_body(
    int t,
    const float* __restrict__ x, const float* __restrict__ state1,
    const float* __restrict__ lnw, const float* __restrict__ lnb,
    const float* __restrict__ cr, const float* __restrict__ ck,
    const float* __restrict__ cv, const float* __restrict__ cg,
    const float* __restrict__ ca, const float* __restrict__ cw,
    __half* __restrict__ abuf, float* __restrict__ state1_out)
{
    const float* xt = x + (size_t)t * HID;
    const float* xp = x + (size_t)(t - 1) * HID;

    float2 v0[4], v1[4];
    float s0 = 0.f, s1 = 0.f;
#pragma unroll
    for (int j = 0; j < 4; j++) {
        int c = threadIdx.x * 2 + j * 512;
        v0[j] = *(const float2*)(xt + c);
        s0 += v0[j].x + v0[j].y;
        v1[j] = t ? *(const float2*)(xp + c) : make_float2(0.f, 0.f);
        s1 += v1[j].x + v1[j].y;
    }
    float mu0 = blk_sum256(s0) * (1.f / HID);
    float mu1 = blk_sum256(s1) * (1.f / HID);
    float q0 = 0.f, q1 = 0.f;
#pragma unroll
    for (int j = 0; j < 4; j++) {
        float d;
        d = v0[j].x - mu0; q0 += d * d;
        d = v0[j].y - mu0; q0 += d * d;
        d = v1[j].x - mu1; q1 += d * d;
        d = v1[j].y - mu1; q1 += d * d;
    }
    float inv0 = rsqrtf(blk_sum256(q0) * (1.f / HID) + 1e-5f);
    float inv1 = rsqrtf(blk_sum256(q1) * (1.f / HID) + 1e-5f);

#pragma unroll
    for (int j = 0; j < 4; j++) {
        int c = threadIdx.x * 2 + j * 512;
        float2 wv = *(const float2*)(lnw + c);
        float2 bv = *(const float2*)(lnb + c);
        float xn0 = (v0[j].x - mu0) * inv0 * wv.x + bv.x;
        float xn1 = (v0[j].y - mu0) * inv0 * wv.y + bv.y;
        float pv0 = t ? (v1[j].x - mu1) * inv1 * wv.x + bv.x : state1[c];
        float pv1 = t ? (v1[j].y - mu1) * inv1 * wv.y + bv.y : state1[c + 1];
        float sx0 = pv0 - xn0, sx1 = pv1 - xn1;

        __half* arow = abuf + (size_t)t * 2 * HID + c;
#pragma unroll
        for (int s = 0; s < 6; s++) {
            const float* coefA = (s == 0) ? cr : (s == 1) ? ck : (s == 2) ? cv
                               : (s == 3) ? cg : (s == 4) ? ca : cw;
            float a0 = xn0 + coefA[c] * sx0;
            float a1 = xn1 + coefA[c + 1] * sx1;
            __half* p = arow + (size_t)s * ASLOT_H;
            if (s == 5) {
                __half h0, l0, h1, l1;
                hsplit(a0, h0, l0);
                hsplit(a1, h1, l1);
                *(__half2*)(p) = __half2(h0, h1);
                *(__half2*)(p + HID) = __half2(l0, l1);
            } else {
                *(__half2*)(p) = __floats2half2_rn(a0, a1);
            }
        }
        if (state1_out && t == T_LEN - 1) {
            state1_out[c] = xn0;
            state1_out[c + 1] = xn1;
        }
    }
}

#define FRONT_BLOCKS (1024 + 9472 + 384)

__global__ void __launch_bounds__(256) front_kernel(
    const float* __restrict__ x, const float* __restrict__ state1,
    const float* __restrict__ lnw, const float* __restrict__ lnb,
    const float* __restrict__ cr, const float* __restrict__ ck,
    const float* __restrict__ cv, const float* __restrict__ cg,
    const float* __restrict__ ca, const float* __restrict__ cw,
    __half* __restrict__ abuf, float* __restrict__ state1_out,
    const float* __restrict__ Wr, const float* __restrict__ Wk,
    const float* __restrict__ Wv, const float* __restrict__ Wo,
    const float* __restrict__ g1, const float* __restrict__ g2,
    const float* __restrict__ a1, const float* __restrict__ w1,
    const float* __restrict__ v1, const float* __restrict__ vf,
    const float* __restrict__ a2, const float* __restrict__ w2,
    const float* __restrict__ v2,
    __half* __restrict__ wbuf, __half* __restrict__ g1buf,
    __half* __restrict__ g2buf, __half* __restrict__ lorabuf,
    __half* __restrict__ upbuf, float* __restrict__ vfout)
{
    __shared__ float tile[64 * 33];
    int bb = blockIdx.x;
    if (bb < 1024) {
        ln_mix_body(bb, x, state1, lnw, lnb, cr, ck, cv, cg, ca, cw, abuf, state1_out);
        return;
    }
    int b = bb - 1024;
    if (b < 8192) {
        int z = b >> 11, rem = b & 2047;
        const float* W = z == 0 ? Wr : z == 1 ? Wk : z == 2 ? Wv : Wo;
        conv_tile2(W, wbuf + (size_t)z * WSLOT_H, HID, HID, rem & 63, rem >> 6, tile, HID);
    } else if (b < 8448) {
        int rem = b - 8192;
        conv_tile2(g1, g1buf, HID, 256, rem & 7, rem >> 3, tile, HID);
    } else if (b < 8704) {
        int rem = b - 8448;
        conv_tile2(g2, g2buf, 256, HID, rem & 63, rem >> 6, tile, 256);
    } else if (b < 8800) {
        int rem = b - 8704;
        conv_tile2(a1, lorabuf, HID, 96, rem % 3, rem / 3, tile, HID);
    } else if (b < 8896) {
        int rem = b - 8800;
        conv_tile2(w1, lorabuf + LSLOT_H, HID, 96, rem % 3, rem / 3, tile, HID);
    } else if (b < 8960) {
        int rem = b - 8896;
        conv_tile2(v1, lorabuf + 2 * LSLOT_H, HID, 64, rem & 1, rem >> 1, tile, HID);
    } else if (b < 9472) {
        if (!vfout) return;
        int rem = b - 8960;
#pragma unroll
        for (int j = 0; j < 4; j++) {
            size_t i = (size_t)rem * 4096 + j * 1024 + threadIdx.x * 4;
            *(float4*)(vfout + i) = *(const float4*)(vf + i);
        }
    } else {
        int rem = b - 9472;
        int z = rem >> 7, sub = rem & 127;
        const float* W = z == 0 ? a2 : z == 1 ? w2 : v2;
        int kmax = (z == 2) ? 64 : 96;
        conv_tile2(W, upbuf + (size_t)z * USLOT_H, 128, HID, sub & 63, sub >> 6, tile, kmax);
    }
}

// ---------------- prep2: kk/k2 + pair scalars + pscan2 packing ----------------
__global__ void __launch_bounds__(256) prep2_kernel(
    const float* __restrict__ k, const float* __restrict__ a,
    const float* __restrict__ w, const float* __restrict__ v,
    const float* __restrict__ r,
    const float* __restrict__ k_k, const float* __restrict__ k_a,
    float* __restrict__ k2out, float* __restrict__ pscan2)
{
    int gw = (blockIdx.x * 256 + threadIdx.x) >> 5;
    int lane = threadIdx.x & 31;
    if (gw >= NPAIR * NHEAD) return;
    int pr = gw >> 5, h = gw & 31;
    int b0 = (2 * pr) * HID + h * HEADD;
    int b1 = b0 + HID;
    int cb = h * HEADD;

    float kA0 = k[b0 + lane], kB0 = k[b0 + lane + 32];
    float qA0 = kA0 * k_k[cb + lane], qB0 = kB0 * k_k[cb + lane + 32];
    float inv0 = 1.f / fmaxf(sqrtf(warp_sum(qA0 * qA0 + qB0 * qB0)), 1e-12f);
    float kkA0 = qA0 * inv0, kkB0 = qB0 * inv0;
    float aA0 = a[b0 + lane], aB0 = a[b0 + lane + 32];
    float k2A0 = kA0 * (1.f + (aA0 - 1.f) * k_a[cb + lane]);
    float k2B0 = kB0 * (1.f + (aB0 - 1.f) * k_a[cb + lane + 32]);
    k2out[b0 + lane] = k2A0;
    k2out[b0 + lane + 32] = k2B0;

    float kA1 = k[b1 + lane], kB1 = k[b1 + lane + 32];
    float qA1 = kA1 * k_k[cb + lane], qB1 = kB1 * k_k[cb + lane + 32];
    float inv1 = 1.f / fmaxf(sqrtf(warp_sum(qA1 * qA1 + qB1 * qB1)), 1e-12f);
    float kkA1 = qA1 * inv1, kkB1 = qB1 * inv1;
    float aA1 = a[b1 + lane], aB1 = a[b1 + lane + 32];
    float k2A1 = kA1 * (1.f + (aA1 - 1.f) * k_a[cb + lane]);
    float k2B1 = kB1 * (1.f + (aB1 - 1.f) * k_a[cb + lane + 32]);
    k2out[b1 + lane] = k2A1;
    k2out[b1 + lane + 32] = k2B1;

    float wA0 = w[b0 + lane], wB0 = w[b0 + lane + 32];
    float kaA0 = kkA0 * aA0, kaB0 = kkB0 * aB0;

    float c1 = warp_sum(kkA1 * kaA0 + kkB1 * kaB0);
    float c2 = warp_sum(kkA1 * k2A0 + kkB1 * k2B0);

    float* P = pscan2 + ((size_t)pr * NHEAD + h) * 1024;
    P[0 * 64 + lane] = kkA0;           P[0 * 64 + lane + 32] = kkB0;
    P[1 * 64 + lane] = kkA1 * wA0;     P[1 * 64 + lane + 32] = kkB1 * wB0;
    P[2 * 64 + lane] = wA0;            P[2 * 64 + lane + 32] = wB0;
    P[3 * 64 + lane] = kaA0;           P[3 * 64 + lane + 32] = kaB0;
    P[4 * 64 + lane] = k2A0;           P[4 * 64 + lane + 32] = k2B0;
    P[5 * 64 + lane] = r[b0 + lane];   P[5 * 64 + lane + 32] = r[b0 + lane + 32];
    P[6 * 64 + lane] = w[b1 + lane];   P[6 * 64 + lane + 32] = w[b1 + lane + 32];
    P[7 * 64 + lane] = kkA1 * aA1;     P[7 * 64 + lane + 32] = kkB1 * aB1;
    P[8 * 64 + lane] = k2A1;           P[8 * 64 + lane + 32] = k2B1;
    P[9 * 64 + lane] = r[b1 + lane];   P[9 * 64 + lane + 32] = r[b1 + lane + 32];
    P[10 * 64 + lane] = v[b0 + lane];  P[10 * 64 + lane + 32] = v[b0 + lane + 32];
    P[11 * 64 + lane] = v[b1 + lane];  P[11 * 64 + lane + 32] = v[b1 + lane + 32];
    if (lane == 0) { P[12 * 64] = c1; P[12 * 64 + 1] = c2; }
}

// ---------------- scan v3.1: two steps per round, full y reduction in-scan ----------------
__global__ void __launch_bounds__(256) scan3_kernel(
    const float* __restrict__ pscan2,
    const float* __restrict__ state2, float* __restrict__ ybuf,
    float* __restrict__ Sout)
{
    int h = blockIdx.x >> 2;
    int q = blockIdx.x & 3;
    int tid = threadIdx.x;
    int wrp = tid >> 5, lane = tid & 31;
    int rsel = lane >> 4, colg = lane & 15;
    int row = q * 16 + 2 * wrp + rsel;

    float4 S = *(const float4*)(state2 + (size_t)h * 4096 + row * 64 + colg * 4);

    __shared__ float buf[2][1024];

    const float* pB = pscan2 + (size_t)h * 1024;
    const size_t pstride = (size_t)NHEAD * 1024;

    ((float4*)buf[0])[tid] = *(const float4*)(pB + tid * 4);
    float4 preA = *(const float4*)(pB + pstride + tid * 4);
    float4 preB;

    for (int pr = 0; pr < NPAIR; pr++) {
        __syncthreads();
        preB = (pr + 2 < NPAIR) ? *(const float4*)(pB + (size_t)(pr + 2) * pstride + tid * 4)
                                : preA;
        const float* b = buf[pr & 1];
        float4 kk4  = *(const float4*)(b + 0 * 64 + colg * 4);
        float4 kkw4 = *(const float4*)(b + 1 * 64 + colg * 4);
        float4 w4   = *(const float4*)(b + 2 * 64 + colg * 4);
        float4 ka4  = *(const float4*)(b + 3 * 64 + colg * 4);
        float4 k4   = *(const float4*)(b + 4 * 64 + colg * 4);
        float4 r4   = *(const float4*)(b + 5 * 64 + colg * 4);
        float4 w14  = *(const float4*)(b + 6 * 64 + colg * 4);
        float4 ka14 = *(const float4*)(b + 7 * 64 + colg * 4);
        float4 k14  = *(const float4*)(b + 8 * 64 + colg * 4);
        float4 r14  = *(const float4*)(b + 9 * 64 + colg * 4);
        float v0 = b[10 * 64 + row];
        float v1 = b[11 * 64 + row];
        float c1 = b[12 * 64];
        float c2 = b[12 * 64 + 1];

        float d0 = S.x * kk4.x + S.y * kk4.y + S.z * kk4.z + S.w * kk4.w;
        float d1 = S.x * kkw4.x + S.y * kkw4.y + S.z * kkw4.z + S.w * kkw4.w;
#pragma unroll
        for (int o = 1; o <= 8; o <<= 1) {
            d0 += __shfl_xor_sync(0xffffffffu, d0, o);
            d1 += __shfl_xor_sync(0xffffffffu, d1, o);
        }
        float p0 = d0;
        float p1 = d1 - p0 * c1 + v0 * c2;

        S.x = S.x * w4.x - p0 * ka4.x + v0 * k4.x;
        S.y = S.y * w4.y - p0 * ka4.y + v0 * k4.y;
        S.z = S.z * w4.z - p0 * ka4.z + v0 * k4.z;
        S.w = S.w * w4.w - p0 * ka4.w + v0 * k4.w;

        float y0 = S.x * r4.x + S.y * r4.y + S.z * r4.z + S.w * r4.w;
        y0 += __shfl_xor_sync(0xffffffffu, y0, 1);
        y0 += __shfl_xor_sync(0xffffffffu, y0, 2);
        y0 += __shfl_xor_sync(0xffffffffu, y0, 4);
        y0 += __shfl_xor_sync(0xffffffffu, y0, 8);
        if (colg == 0)
            ybuf[(size_t)(2 * pr) * HID + h * HEADD + row] = y0;

        if (pr + 1 < NPAIR)
            ((float4*)buf[(pr + 1) & 1])[tid] = preA;
        preA = preB;

        S.x = S.x * w14.x - p1 * ka14.x + v1 * k14.x;
        S.y = S.y * w14.y - p1 * ka14.y + v1 * k14.y;
        S.z = S.z * w14.z - p1 * ka14.z + v1 * k14.z;
        S.w = S.w * w14.w - p1 * ka14.w + v1 * k14.w;

        float y1 = S.x * r14.x + S.y * r14.y + S.z * r14.z + S.w * r14.w;
        y1 += __shfl_xor_sync(0xffffffffu, y1, 1);
        y1 += __shfl_xor_sync(0xffffffffu, y1, 2);
        y1 += __shfl_xor_sync(0xffffffffu, y1, 4);
        y1 += __shfl_xor_sync(0xffffffffu, y1, 8);
        if (colg == 0)
            ybuf[(size_t)(2 * pr + 1) * HID + h * HEADD + row] = y1;
    }
    *(float4*)(Sout + (size_t)h * 4096 + row * 64 + colg * 4) = S;
}

// ---------------- groupnorm + rkv + gate -> single-plane fp16 into abuf ----------------
__global__ void __launch_bounds__(256) post_kernel(
    const float* __restrict__ y, const float* __restrict__ r,
    const float* __restrict__ k2, const float* __restrict__ v,
    const float* __restrict__ g, const float* __restrict__ r_k,
    const float* __restrict__ lnxw, const float* __restrict__ lnxb,
    __half* __restrict__ zsplit)
{
    int gw = (blockIdx.x * 256 + threadIdx.x) >> 5;
    int lane = threadIdx.x & 31;
    if (gw >= T_LEN * NHEAD) return;
    int t = gw >> 5, h = gw & 31;
    int base = t * HID + h * HEADD;
    int cb = h * HEADD;

    float y0 = y[base + lane], y1 = y[base + lane + 32];

    float mu = warp_sum(y0 + y1) * (1.f / HEADD);
    float d0 = y0 - mu, d1 = y1 - mu;
    float var = warp_sum(d0 * d0 + d1 * d1) * (1.f / HEADD);
    float inv = rsqrtf(var + 0.00064f);

    float rs = warp_sum(r[base + lane] * k2[base + lane] * r_k[cb + lane] +
                        r[base + lane + 32] * k2[base + lane + 32] * r_k[cb + lane + 32]);

    float z0 = (d0 * inv * lnxw[cb + lane] + lnxb[cb + lane] + rs * v[base + lane]) * g[base + lane];
    float z1 = (d1 * inv * lnxw[cb + lane + 32] + lnxb[cb + lane + 32] + rs * v[base + lane + 32]) * g[base + lane + 32];

    size_t zb = (size_t)t * 2 * HID;
    zsplit[zb + cb + lane] = __float2half_rn(z0);
    zsplit[zb + cb + lane + 32] = __float2half_rn(z1);
}

// ---------------- host launcher ----------------
extern "C" void kernel_launch(void* const* d_in, const int* in_sizes, int n_in,
                              void* d_out, int out_size)
{
    const float* x       = (const float*)d_in[0];
    const float* state1  = (const float*)d_in[1];
    const float* state2  = (const float*)d_in[2];
    const float* v_first = (const float*)d_in[3];
    const float* ln1_w   = (const float*)d_in[4];
    const float* ln1_b   = (const float*)d_in[5];
    const float* x_r     = (const float*)d_in[6];
    const float* x_w     = (const float*)d_in[7];
    const float* x_k     = (const float*)d_in[8];
    const float* x_v     = (const float*)d_in[9];
    const float* x_a     = (const float*)d_in[10];
    const float* x_g     = (const float*)d_in[11];
    const float* Wr      = (const float*)d_in[12];
    const float* Wk      = (const float*)d_in[13];
    const float* Wv      = (const float*)d_in[14];
    const float* Wo      = (const float*)d_in[15];
    const float* w0      = (const float*)d_in[16];
    const float* w1      = (const float*)d_in[17];
    const float* w2      = (const float*)d_in[18];
    const float* a0      = (const float*)d_in[19];
    const float* a1      = (const float*)d_in[20];
    const float* a2      = (const float*)d_in[21];
    const float* v0      = (const float*)d_in[22];
    const float* v1      = (const float*)d_in[23];
    const float* v2      = (const float*)d_in[24];
    const float* g1      = (const float*)d_in[25];
    const float* g2      = (const float*)d_in[26];
    const float* k_k     = (const float*)d_in[27];
    const float* k_a     = (const float*)d_in[28];
    const float* r_k     = (const float*)d_in[29];
    const float* ln_x_w  = (const float*)d_in[30];
    const float* ln_x_b  = (const float*)d_in[31];

    float* sc = nullptr;      cudaGetSymbolAddress((void**)&sc, g_scratch);
    float* pscan2 = nullptr;  cudaGetSymbolAddress((void**)&pscan2, g_pscan2);
    float* ybuf = nullptr;    cudaGetSymbolAddress((void**)&ybuf, g_y);
    __half* abuf = nullptr;   cudaGetSymbolAddress((void**)&abuf, g_abuf);
    __half* wbuf = nullptr;   cudaGetSymbolAddress((void**)&wbuf, g_wbuf);
    __half* g1buf = nullptr;  cudaGetSymbolAddress((void**)&g1buf, g_g1buf);
    __half* g2buf = nullptr;  cudaGetSymbolAddress((void**)&g2buf, g_g2buf);
    __half* ghbuf = nullptr;  cudaGetSymbolAddress((void**)&ghbuf, g_ghbuf);
    __half* lorabuf = nullptr; cudaGetSymbolAddress((void**)&lorabuf, g_lorabuf);
    __half* upbuf = nullptr;  cudaGetSymbolAddress((void**)&upbuf, g_upbuf);
    __half* hbuf_h = nullptr; cudaGetSymbolAddress((void**)&hbuf_h, g_hbuf_h);

    cudaFuncSetAttribute(mm128_kernel, cudaFuncAttributeMaxDynamicSharedMemorySize, MM_SMEM);
    cudaFuncSetAttribute(mm64_kernel, cudaFuncAttributeMaxDynamicSharedMemorySize, MM64_SMEM);

#define SLOT(s) (sc + (size_t)(s) * NTOK_EL)

    float* out = (float*)d_out;
    const int OFF_OUT = 0;
    const int OFF_S1  = NTOK_EL;
    const int OFF_S2  = OFF_S1 + HID;
    const int OFF_VF  = OFF_S2 + NHEAD * HEADD * HEADD;
    const int TOTAL   = OFF_VF + NTOK_EL;
    bool full = (out_size >= TOTAL);

    float* s1_out = full ? out + OFF_S1 : nullptr;
    float* s2_out = full ? out + OFF_S2 : SLOT(S_TMP);
    float* vf_out = full ? out + OFF_VF : nullptr;

    // 1. front: ln_mix + all weight conversions + v_first passthrough
    front_kernel<<<FRONT_BLOCKS, 256>>>(x, state1, ln1_w, ln1_b,
                                        x_r, x_k, x_v, x_g, x_a, x_w,
                                        abuf, s1_out,
                                        Wr, Wk, Wv, Wo, g1, g2, a1, w1, v1, v_first,
                                        a2, w2, v2,
                                        wbuf, g1buf, g2buf, lorabuf, upbuf, vf_out);

    // 2. mega-batch on 64-row tiles (better wave packing):
    //    r,k,v (fp32) + g-down (sigmoid fp16) + a/w/v-down (fp16)
    {
        MMJobs jobs;
        jobs.j[0] = { abuf,             wbuf,               SLOT(S_R), nullptr, nullptr, HID, HID, 2*HID, HID, 0, 1 };
        jobs.j[1] = { abuf + ASLOT_H,   wbuf + WSLOT_H,     SLOT(S_K), nullptr, nullptr, HID, HID, 2*HID, HID, 0, 1 };
        jobs.j[2] = { abuf + 2*ASLOT_H, wbuf + 2*WSLOT_H,   SLOT(S_V), nullptr, nullptr, HID, HID, 2*HID, HID, 0, 1 };
        jobs.j[3] = { abuf + 3*ASLOT_H, g1buf,              (float*)ghbuf, nullptr, nullptr, 256, HID, 2*HID, 256, 4, 1 };
        jobs.j[4] = { abuf + 4*ASLOT_H, lorabuf,            (float*)hbuf_h, nullptr, nullptr, 128, HID, 2*HID, 384, 5, 1 };
        jobs.j[5] = { abuf + 5*ASLOT_H, lorabuf + LSLOT_H,  (float*)(hbuf_h + 128), nullptr, nullptr, 128, HID, 2*HID, 384, 6, 2 };
        jobs.j[6] = { abuf + 2*ASLOT_H, lorabuf + 2*LSLOT_H, (float*)(hbuf_h + 256), nullptr, nullptr, 128, HID, 2*HID, 384, 5, 1 };
        mm64_kernel<<<dim3(16, 16, 7), 256, MM64_SMEM>>>(jobs);
    }

    // 3. batch2: g-up + a-up + w-up + v-up (mm128; 512 CTAs = 2 full waves)
    {
        MMJobs jobs;
        jobs.j[0] = { ghbuf,        g2buf,              SLOT(S_G), nullptr, nullptr, HID, 256, 256, HID, 0, 1 };
        jobs.j[1] = { hbuf_h,       upbuf,              SLOT(S_R) - NTOK_EL + 6 * NTOK_EL, nullptr, a0, HID, 128, 384, HID, 7, 1 };
        jobs.j[1].C = sc + (size_t)6 * NTOK_EL;   // S_A
        jobs.j[2] = { hbuf_h + 128, upbuf + USLOT_H,    sc + (size_t)7 * NTOK_EL, nullptr, w0, HID, 128, 384, HID, 8, 1 };
        jobs.j[3] = { hbuf_h + 256, upbuf + 2*USLOT_H,  SLOT(S_V), v_first, v0,    HID, 128, 384, HID, 9, 1 };
        mm128_kernel<<<dim3(16, 8, 4), 256, MM_SMEM>>>(jobs, 4);
    }

    // 4. prep pairs
    prep2_kernel<<<(NPAIR * NHEAD * 32 + 255) / 256, 256>>>(
        SLOT(S_K), sc + (size_t)6 * NTOK_EL, sc + (size_t)7 * NTOK_EL,
        SLOT(S_V), SLOT(S_R),
        k_k, k_a, SLOT(S_K2), pscan2);

    // 5. two-step scan (full y reduction in-scan)
    scan3_kernel<<<128, 256>>>(pscan2, state2, ybuf, s2_out);

    // 6. groupnorm + rkv + gate -> single-plane fp16 into abuf slot 0
    post_kernel<<<(T_LEN * NHEAD * 32 + 255) / 256, 256>>>(
        ybuf, SLOT(S_R), SLOT(S_K2), SLOT(S_V), SLOT(S_G),
        r_k, ln_x_w, ln_x_b, abuf);

    // 7. out = x + z@Wo (single-plane, residual fused)
    {
        MMJobs jobs;
        jobs.j[0] = { abuf, wbuf + 3*WSLOT_H, out + OFF_OUT, x, nullptr, HID, HID, 2*HID, HID, 1, 1 };
        for (int i = 1; i < 7; i++) jobs.j[i] = jobs.j[0];
        mm64_kernel<<<dim3(16, 16, 1), 256, MM64_SMEM>>>(jobs);
    }
}

// round 17
// speedup vs baseline: 1.0736x; 1.0736x over previous
#include <cuda_runtime.h>
#include <cuda_fp16.h>
#include <math.h>
#include <stdint.h>

#define T_LEN 1024
#define HID   2048
#define NHEAD 32
#define HEADD 64
#define NTOK_EL (T_LEN * HID)
#define NPAIR (T_LEN / 2)

#define ASLOT_H ((size_t)T_LEN * 2 * HID)   // activation slot: [M, 2K] fp16 (hi plane used)
#define WSLOT_H ((size_t)HID * HID)         // big W slot: [N, K] fp16
#define LSLOT_H ((size_t)128 * HID)         // lora-down W slot (padded 128 rows)
#define USLOT_H ((size_t)HID * 128)         // lora-up W slot: [2048, 128] fp16 padded

// ---------------- static device scratch ----------------
__device__ float g_scratch[8u * (unsigned)NTOK_EL];
__device__ float g_pscan2[(size_t)NPAIR * NHEAD * 1024];
__device__ float g_y[(size_t)T_LEN * HID];
__device__ __align__(256) __half g_abuf[6 * ASLOT_H];
__device__ __align__(256) __half g_wbuf[4 * WSLOT_H];
__device__ __align__(256) __half g_g1buf[(size_t)256 * HID];
__device__ __align__(256) __half g_g2buf[(size_t)HID * 256];
__device__ __align__(256) __half g_ghbuf[(size_t)T_LEN * 256];
__device__ __align__(256) __half g_lorabuf[3 * LSLOT_H];
__device__ __align__(256) __half g_upbuf[3 * USLOT_H];
__device__ __align__(256) __half g_hbuf_h[(size_t)T_LEN * 384];

#define S_R   0
#define S_K   1
#define S_V   2
#define S_K2  3
#define S_G   4
#define S_TMP 5
#define S_A   6
#define S_W   7

// ---------------- helpers ----------------
__device__ __forceinline__ float blk_sum256(float v) {
    __shared__ float sh[8];
    int tid = threadIdx.x;
#pragma unroll
    for (int o = 16; o; o >>= 1) v += __shfl_xor_sync(0xffffffffu, v, o);
    if ((tid & 31) == 0) sh[tid >> 5] = v;
    __syncthreads();
    if (tid == 0) {
        float s = 0.f;
#pragma unroll
        for (int i = 0; i < 8; i++) s += sh[i];
        sh[0] = s;
    }
    __syncthreads();
    float r = sh[0];
    __syncthreads();
    return r;
}

__device__ __forceinline__ float warp_sum(float v) {
#pragma unroll
    for (int o = 16; o; o >>= 1) v += __shfl_xor_sync(0xffffffffu, v, o);
    return v;
}

__device__ __forceinline__ float sigmoidf(float v) {
    return 1.f / (1.f + __expf(-v));
}

__device__ __forceinline__ uint32_t smem_u32(const void* p) {
    uint32_t a;
    asm("{ .reg .u64 t; cvta.to.shared.u64 t, %1; cvt.u32.u64 %0, t; }" : "=r"(a) : "l"(p));
    return a;
}

// ======================= mma.sync fp16 GEMM =======================
#define MMK_STRIDE 80
#define MMK_TILE   (128 * MMK_STRIDE)
#define STAGE_BYTES (3 * MMK_TILE)
#define MM_SMEM (3 * STAGE_BYTES)

// modes: 0 fp32 store | 1 +Res fp32 | 4 sigmoid->fp16 | 5 fp16 | 6 tanh->fp16
//        7 sigmoid(bias+x)->fp32 | 8 exp(-.606531*sigmoid(bias+x))->fp32
//        9 C = C + (Res-C)*sigmoid(bias+x) | 10 atomicAdd fp32 (split-K partial)
struct MMJob {
    const __half* A; const __half* B; float* C; const float* Res; const float* bias;
    int N; int K; int lda; int ldc; int mode; int planes; int koff; int nkc;
};
struct MMJobs { MMJob j[10]; };

__device__ __forceinline__ void cp16(uint32_t dst, const void* src) {
    asm volatile("cp.async.cg.shared.global [%0], [%1], 16;" :: "r"(dst), "l"(src));
}

__device__ __forceinline__ void ldsm4(uint32_t* r, uint32_t a) {
    asm volatile("ldmatrix.sync.aligned.m8n8.x4.shared.b16 {%0,%1,%2,%3}, [%4];"
                 : "=r"(r[0]), "=r"(r[1]), "=r"(r[2]), "=r"(r[3]) : "r"(a));
}

__device__ __forceinline__ void mma16816(float* c, const uint32_t* a, const uint32_t* b) {
    asm volatile(
        "mma.sync.aligned.m16n8k16.row.col.f32.f16.f16.f32 "
        "{%0,%1,%2,%3}, {%4,%5,%6,%7}, {%8,%9}, {%0,%1,%2,%3};"
        : "+f"(c[0]), "+f"(c[1]), "+f"(c[2]), "+f"(c[3])
        : "r"(a[0]), "r"(a[1]), "r"(a[2]), "r"(a[3]), "r"(b[0]), "r"(b[1]));
}

__device__ __forceinline__ void mm_epilogue(
    const MMJob& job, int row, int col, float2 v0, float2 v1)
{
    float* C = job.C;
    int ldc = job.ldc;
    int mode = job.mode;
    if (mode == 10) {
        atomicAdd(C + (size_t)row * ldc + col, v0.x);
        atomicAdd(C + (size_t)row * ldc + col + 1, v0.y);
        atomicAdd(C + (size_t)(row + 8) * ldc + col, v1.x);
        atomicAdd(C + (size_t)(row + 8) * ldc + col + 1, v1.y);
        return;
    }
    if (mode == 4 || mode == 5 || mode == 6) {
        __half* Ch = (__half*)C;
        if (mode == 4) {
            v0.x = sigmoidf(v0.x); v0.y = sigmoidf(v0.y);
            v1.x = sigmoidf(v1.x); v1.y = sigmoidf(v1.y);
        } else if (mode == 6) {
            v0.x = tanhf(v0.x); v0.y = tanhf(v0.y);
            v1.x = tanhf(v1.x); v1.y = tanhf(v1.y);
        }
        *(__half2*)(Ch + (size_t)row * ldc + col) = __floats2half2_rn(v0.x, v0.y);
        *(__half2*)(Ch + (size_t)(row + 8) * ldc + col) = __floats2half2_rn(v1.x, v1.y);
        return;
    }
    if (mode == 1) {
        const float2 r0 = *(const float2*)(job.Res + (size_t)row * ldc + col);
        const float2 r1 = *(const float2*)(job.Res + (size_t)(row + 8) * ldc + col);
        v0.x += r0.x; v0.y += r0.y;
        v1.x += r1.x; v1.y += r1.y;
    } else if (mode == 7 || mode == 8 || mode == 9) {
        float b0 = job.bias[col], b1 = job.bias[col + 1];
        float s00 = sigmoidf(b0 + v0.x), s01 = sigmoidf(b1 + v0.y);
        float s10 = sigmoidf(b0 + v1.x), s11 = sigmoidf(b1 + v1.y);
        if (mode == 7) {
            v0 = make_float2(s00, s01); v1 = make_float2(s10, s11);
        } else if (mode == 8) {
            v0 = make_float2(__expf(-0.606531f * s00), __expf(-0.606531f * s01));
            v1 = make_float2(__expf(-0.606531f * s10), __expf(-0.606531f * s11));
        } else {
            float2 c0 = *(const float2*)(C + (size_t)row * ldc + col);
            float2 c1 = *(const float2*)(C + (size_t)(row + 8) * ldc + col);
            const float2 f0 = *(const float2*)(job.Res + (size_t)row * ldc + col);
            const float2 f1 = *(const float2*)(job.Res + (size_t)(row + 8) * ldc + col);
            v0 = make_float2(c0.x + (f0.x - c0.x) * s00, c0.y + (f0.y - c0.y) * s01);
            v1 = make_float2(c1.x + (f1.x - c1.x) * s10, c1.y + (f1.y - c1.y) * s11);
        }
    }
    *(float2*)(C + (size_t)row * ldc + col) = v0;
    *(float2*)(C + (size_t)(row + 8) * ldc + col) = v1;
}

__global__ void __launch_bounds__(256, 2) mm128_kernel(MMJobs jobs)
{
    extern __shared__ __align__(16) char smem[];
    uint32_t sbase = smem_u32(smem);

    const MMJob job = jobs.j[blockIdx.z];
    const int N = job.N;
    int n0 = blockIdx.x * 128;
    if (n0 >= N) return;
    int m0 = blockIdx.y * 128;

    const __half* Ab = job.A;
    const __half* Bb = job.B;
    const int K = job.K;        // B row stride / lo-plane offset
    const int lda = job.lda;
    const int koff = job.koff;
    const int nk = job.nkc;
    const int planes = job.planes;

    int tid = threadIdx.x;
    int wid = tid >> 5, lane = tid & 31;
    int g = lane >> 2, tig = lane & 3;
    int warp_m = wid >> 2;
    int warp_n = wid & 3;

    float acc[4][4][4];
#pragma unroll
    for (int i = 0; i < 4; i++)
#pragma unroll
        for (int j = 0; j < 4; j++)
#pragma unroll
            for (int q = 0; q < 4; q++) acc[i][j][q] = 0.f;

    auto load_stage = [&](int s, int kc) {
        uint32_t st = sbase + s * STAGE_BYTES;
        int k0 = koff + (kc << 5);
#pragma unroll
        for (int it = 0; it < 2; it++) {
            int idx = tid + it * 256;
            int r = idx >> 2, c = idx & 3;
            cp16(st + r * MMK_STRIDE + c * 16, Ab + ((size_t)(m0 + r) * lda + k0 + c * 8));
        }
        if (planes == 2) {
#pragma unroll
            for (int it = 0; it < 2; it++) {
                int idx = tid + it * 256;
                int r = idx >> 2, c = idx & 3;
                cp16(st + MMK_TILE + r * MMK_STRIDE + c * 16,
                     Ab + ((size_t)(m0 + r) * lda + K + k0 + c * 8));
            }
        }
#pragma unroll
        for (int it = 0; it < 2; it++) {
            int idx = tid + it * 256;
            int r = idx >> 2, c = idx & 3;
            cp16(st + 2 * MMK_TILE + r * MMK_STRIDE + c * 16,
                 Bb + ((size_t)(n0 + r) * K + k0 + c * 8));
        }
        asm volatile("cp.async.commit_group;" ::: "memory");
    };

    load_stage(0, 0);
    if (nk > 1) load_stage(1, 1);
    else asm volatile("cp.async.commit_group;" ::: "memory");

    int aRowSel = (lane & 15);
    int aColSel = (lane & 16) ? 16 : 0;
    int bRowSel = ((lane & 16) ? 8 : 0) + (lane & 7);
    int bColSel = (lane & 8) ? 16 : 0;

    for (int kc = 0; kc < nk; kc++) {
        asm volatile("cp.async.wait_group 1;" ::: "memory");
        __syncthreads();
        if (kc + 2 < nk) load_stage((kc + 2) % 3, kc + 2);
        else asm volatile("cp.async.commit_group;" ::: "memory");

        uint32_t st = sbase + (kc % 3) * STAGE_BYTES;
#pragma unroll
        for (int ks = 0; ks < 2; ks++) {
            uint32_t afr[4][4], bfr[2][4];
#pragma unroll
            for (int ap = 0; ap < 2; ap++) {
                uint32_t addr = st + 2 * MMK_TILE
                                + (uint32_t)(warp_n * 32 + ap * 16 + bRowSel) * MMK_STRIDE
                                + ks * 32 + bColSel;
                ldsm4(bfr[ap], addr);
            }
#pragma unroll
            for (int am = 0; am < 4; am++) {
                uint32_t addr = st + (uint32_t)(warp_m * 64 + am * 16 + aRowSel) * MMK_STRIDE
                                + ks * 32 + aColSel;
                ldsm4(afr[am], addr);
            }
#pragma unroll
            for (int am = 0; am < 4; am++) {
                mma16816(acc[am][0], afr[am], &bfr[0][0]);
                mma16816(acc[am][1], afr[am], &bfr[0][2]);
                mma16816(acc[am][2], afr[am], &bfr[1][0]);
                mma16816(acc[am][3], afr[am], &bfr[1][2]);
            }
            if (planes == 2) {
#pragma unroll
                for (int am = 0; am < 4; am++) {
                    uint32_t addr = st + MMK_TILE
                                    + (uint32_t)(warp_m * 64 + am * 16 + aRowSel) * MMK_STRIDE
                                    + ks * 32 + aColSel;
                    ldsm4(afr[am], addr);
                }
#pragma unroll
                for (int am = 0; am < 4; am++) {
                    mma16816(acc[am][0], afr[am], &bfr[0][0]);
                    mma16816(acc[am][1], afr[am], &bfr[0][2]);
                    mma16816(acc[am][2], afr[am], &bfr[1][0]);
                    mma16816(acc[am][3], afr[am], &bfr[1][2]);
                }
            }
        }
    }

    __syncthreads();

#pragma unroll
    for (int am = 0; am < 4; am++) {
#pragma unroll
        for (int an = 0; an < 4; an++) {
            int row = m0 + warp_m * 64 + am * 16 + g;
            int col = n0 + warp_n * 32 + an * 8 + tig * 2;
            mm_epilogue(job, row, col,
                        make_float2(acc[am][an][0], acc[am][an][1]),
                        make_float2(acc[am][an][2], acc[am][an][3]));
        }
    }
}

// ---------------- mm64: batched 64x128 tile variant (tail GEMMs) ----------------
#define MM64_A_TILE (64 * MMK_STRIDE)
#define MM64_STAGE  (2 * MM64_A_TILE + MMK_TILE)
#define MM64_SMEM   (3 * MM64_STAGE)

__global__ void __launch_bounds__(256, 2) mm64_kernel(MMJobs jobs)
{
    extern __shared__ __align__(16) char smem[];
    uint32_t sbase = smem_u32(smem);

    const MMJob job = jobs.j[blockIdx.z];
    const int N = job.N;
    int n0 = blockIdx.x * 128;
    if (n0 >= N) return;
    int m0 = blockIdx.y * 64;

    const __half* Ab = job.A;
    const __half* Bb = job.B;
    const int K = job.K;
    const int lda = job.lda;
    const int koff = job.koff;
    const int nk = job.nkc;
    const int planes = job.planes;

    int tid = threadIdx.x;
    int wid = tid >> 5, lane = tid & 31;
    int g = lane >> 2, tig = lane & 3;
    int warp_m = wid >> 2;
    int warp_n = wid & 3;

    float acc[2][4][4];
#pragma unroll
    for (int i = 0; i < 2; i++)
#pragma unroll
        for (int j = 0; j < 4; j++)
#pragma unroll
            for (int q = 0; q < 4; q++) acc[i][j][q] = 0.f;

    auto load_stage = [&](int s, int kc) {
        uint32_t st = sbase + s * MM64_STAGE;
        int k0 = koff + (kc << 5);
        {
            int r = tid >> 2, c = tid & 3;
            cp16(st + r * MMK_STRIDE + c * 16, Ab + ((size_t)(m0 + r) * lda + k0 + c * 8));
        }
        if (planes == 2) {
            int r = tid >> 2, c = tid & 3;
            cp16(st + MM64_A_TILE + r * MMK_STRIDE + c * 16,
                 Ab + ((size_t)(m0 + r) * lda + K + k0 + c * 8));
        }
#pragma unroll
        for (int it = 0; it < 2; it++) {
            int idx = tid + it * 256;
            int r = idx >> 2, c = idx & 3;
            cp16(st + 2 * MM64_A_TILE + r * MMK_STRIDE + c * 16,
                 Bb + ((size_t)(n0 + r) * K + k0 + c * 8));
        }
        asm volatile("cp.async.commit_group;" ::: "memory");
    };

    load_stage(0, 0);
    if (nk > 1) load_stage(1, 1);
    else asm volatile("cp.async.commit_group;" ::: "memory");

    int aRowSel = (lane & 15);
    int aColSel = (lane & 16) ? 16 : 0;
    int bRowSel = ((lane & 16) ? 8 : 0) + (lane & 7);
    int bColSel = (lane & 8) ? 16 : 0;

    for (int kc = 0; kc < nk; kc++) {
        asm volatile("cp.async.wait_group 1;" ::: "memory");
        __syncthreads();
        if (kc + 2 < nk) load_stage((kc + 2) % 3, kc + 2);
        else asm volatile("cp.async.commit_group;" ::: "memory");

        uint32_t st = sbase + (kc % 3) * MM64_STAGE;
#pragma unroll
        for (int ks = 0; ks < 2; ks++) {
            uint32_t afr[2][4], bfr[2][4];
#pragma unroll
            for (int ap = 0; ap < 2; ap++) {
                uint32_t addr = st + 2 * MM64_A_TILE
                                + (uint32_t)(warp_n * 32 + ap * 16 + bRowSel) * MMK_STRIDE
                                + ks * 32 + bColSel;
                ldsm4(bfr[ap], addr);
            }
#pragma unroll
            for (int am = 0; am < 2; am++) {
                uint32_t addr = st + (uint32_t)(warp_m * 32 + am * 16 + aRowSel) * MMK_STRIDE
                                + ks * 32 + aColSel;
                ldsm4(afr[am], addr);
            }
#pragma unroll
            for (int am = 0; am < 2; am++) {
                mma16816(acc[am][0], afr[am], &bfr[0][0]);
                mma16816(acc[am][1], afr[am], &bfr[0][2]);
                mma16816(acc[am][2], afr[am], &bfr[1][0]);
                mma16816(acc[am][3], afr[am], &bfr[1][2]);
            }
            if (planes == 2) {
#pragma unroll
                for (int am = 0; am < 2; am++) {
                    uint32_t addr = st + MM64_A_TILE
                                    + (uint32_t)(warp_m * 32 + am * 16 + aRowSel) * MMK_STRIDE
                                    + ks * 32 + aColSel;
                    ldsm4(afr[am], addr);
                }
#pragma unroll
                for (int am = 0; am < 2; am++) {
                    mma16816(acc[am][0], afr[am], &bfr[0][0]);
                    mma16816(acc[am][1], afr[am], &bfr[0][2]);
                    mma16816(acc[am][2], afr[am], &bfr[1][0]);
                    mma16816(acc[am][3], afr[am], &bfr[1][2]);
                }
            }
        }
    }

    __syncthreads();

#pragma unroll
    for (int am = 0; am < 2; am++) {
#pragma unroll
        for (int an = 0; an < 4; an++) {
            int row = m0 + warp_m * 32 + am * 16 + g;
            int col = n0 + warp_n * 32 + an * 8 + tig * 2;
            mm_epilogue(job, row, col,
                        make_float2(acc[am][an][0], acc[am][an][1]),
                        make_float2(acc[am][an][2], acc[am][an][3]));
        }
    }
}

// ---------------- front-end: ln_mix + weight conversions + v_first copy + zero-init --
__device__ __forceinline__ void conv_tile2(const float* __restrict__ W, __half* __restrict__ out,
                                           int K, int N, int bx, int by, float* tile,
                                           int kmax)
{
    int k0 = by * 64, n0 = bx * 32;
    int tid = threadIdx.x;
#pragma unroll
    for (int it = 0; it < 8; it++) {
        int i = tid + it * 256;
        int r = i >> 5, c = i & 31;
        tile[r * 33 + c] = (k0 + r < kmax) ? W[(size_t)(k0 + r) * N + n0 + c] : 0.f;
    }
    __syncthreads();
    int nl = tid >> 3;
    int kq = (tid & 7) * 8;
    __half h8[8];
#pragma unroll
    for (int j = 0; j < 8; j++)
        h8[j] = __float2half_rn(tile[(kq + j) * 33 + nl]);
    *(uint4*)(out + (size_t)(n0 + nl) * K + k0 + kq) = *(uint4*)h8;
}

__device__ void ln_mix_body(
    int t,
    const float* __restrict__ x, const float* __restrict__ state1,
    const float* __restrict__ lnw, const float* __restrict__ lnb,
    const float* __restrict__ cr, const float* __restrict__ ck,
    const float* __restrict__ cv, const float* __restrict__ cg,
    const float* __restrict__ ca, const float* __restrict__ cw,
    __half* __restrict__ abuf, float* __restrict__ state1_out)
{
    const float* xt = x + (size_t)t * HID;
    const float* xp = x + (size_t)(t - 1) * HID;

    float2 v0[4], v1[4];
    float s0 = 0.f, s1 = 0.f;
#pragma unroll
    for (int j = 0; j < 4; j++) {
        int c = threadIdx.x * 2 + j * 512;
        v0[j] = *(const float2*)(xt + c);
        s0 += v0[j].x + v0[j].y;
        v1[j] = t ? *(const float2*)(xp + c) : make_float2(0.f, 0.f);
        s1 += v1[j].x + v1[j].y;
    }
    float mu0 = blk_sum256(s0) * (1.f / HID);
    float mu1 = blk_sum256(s1) * (1.f / HID);
    float q0 = 0.f, q1 = 0.f;
#pragma unroll
    for (int j = 0; j < 4; j++) {
        float d;
        d = v0[j].x - mu0; q0 += d * d;
        d = v0[j].y - mu0; q0 += d * d;
        d = v1[j].x - mu1; q1 += d * d;
        d = v1[j].y - mu1; q1 += d * d;
    }
    float inv0 = rsqrtf(blk_sum256(q0) * (1.f / HID) + 1e-5f);
    float inv1 = rsqrtf(blk_sum256(q1) * (1.f / HID) + 1e-5f);

#pragma unroll
    for (int j = 0; j < 4; j++) {
        int c = threadIdx.x * 2 + j * 512;
        float2 wv = *(const float2*)(lnw + c);
        float2 bv = *(const float2*)(lnb + c);
        float xn0 = (v0[j].x - mu0) * inv0 * wv.x + bv.x;
        float xn1 = (v0[j].y - mu0) * inv0 * wv.y + bv.y;
        float pv0 = t ? (v1[j].x - mu1) * inv1 * wv.x + bv.x : state1[c];
        float pv1 = t ? (v1[j].y - mu1) * inv1 * wv.y + bv.y : state1[c + 1];
        float sx0 = pv0 - xn0, sx1 = pv1 - xn1;

        __half* arow = abuf + (size_t)t * 2 * HID + c;
#pragma unroll
        for (int s = 0; s < 6; s++) {
            const float* coefA = (s == 0) ? cr : (s == 1) ? ck : (s == 2) ? cv
                               : (s == 3) ? cg : (s == 4) ? ca : cw;
            float a0 = xn0 + coefA[c] * sx0;
            float a1 = xn1 + coefA[c + 1] * sx1;
            *(__half2*)(arow + (size_t)s * ASLOT_H) = __floats2half2_rn(a0, a1);
        }
        if (state1_out && t == T_LEN - 1) {
            state1_out[c] = xn0;
            state1_out[c + 1] = xn1;
        }
    }
}

#define FRONT_BLOCKS (1024 + 9472 + 384 + 1536)

__global__ void __launch_bounds__(256) front_kernel(
    const float* __restrict__ x, const float* __restrict__ state1,
    const float* __restrict__ lnw, const float* __restrict__ lnb,
    const float* __restrict__ cr, const float* __restrict__ ck,
    const float* __restrict__ cv, const float* __restrict__ cg,
    const float* __restrict__ ca, const float* __restrict__ cw,
    __half* __restrict__ abuf, float* __restrict__ state1_out,
    const float* __restrict__ Wr, const float* __restrict__ Wk,
    const float* __restrict__ Wv, const float* __restrict__ Wo,
    const float* __restrict__ g1, const float* __restrict__ g2,
    const float* __restrict__ a1, const float* __restrict__ w1,
    const float* __restrict__ v1, const float* __restrict__ vf,
    const float* __restrict__ a2, const float* __restrict__ w2,
    const float* __restrict__ v2,
    __half* __restrict__ wbuf, __half* __restrict__ g1buf,
    __half* __restrict__ g2buf, __half* __restrict__ lorabuf,
    __half* __restrict__ upbuf, float* __restrict__ vfout,
    float* __restrict__ zbuf)
{
    __shared__ float tile[64 * 33];
    int bb = blockIdx.x;
    if (bb < 1024) {
        ln_mix_body(bb, x, state1, lnw, lnb, cr, ck, cv, cg, ca, cw, abuf, state1_out);
        return;
    }
    int b = bb - 1024;
    if (b < 8192) {
        int z = b >> 11, rem = b & 2047;
        const float* W = z == 0 ? Wr : z == 1 ? Wk : z == 2 ? Wv : Wo;
        conv_tile2(W, wbuf + (size_t)z * WSLOT_H, HID, HID, rem & 63, rem >> 6, tile, HID);
    } else if (b < 8448) {
        int rem = b - 8192;
        conv_tile2(g1, g1buf, HID, 256, rem & 7, rem >> 3, tile, HID);
    } else if (b < 8704) {
        int rem = b - 8448;
        conv_tile2(g2, g2buf, 256, HID, rem & 63, rem >> 6, tile, 256);
    } else if (b < 8800) {
        int rem = b - 8704;
        conv_tile2(a1, lorabuf, HID, 96, rem % 3, rem / 3, tile, HID);
    } else if (b < 8896) {
        int rem = b - 8800;
        conv_tile2(w1, lorabuf + LSLOT_H, HID, 96, rem % 3, rem / 3, tile, HID);
    } else if (b < 8960) {
        int rem = b - 8896;
        conv_tile2(v1, lorabuf + 2 * LSLOT_H, HID, 64, rem & 1, rem >> 1, tile, HID);
    } else if (b < 9472) {
        if (!vfout) return;
        int rem = b - 8960;
#pragma unroll
        for (int j = 0; j < 4; j++) {
            size_t i = (size_t)rem * 4096 + j * 1024 + threadIdx.x * 4;
            *(float4*)(vfout + i) = *(const float4*)(vf + i);
        }
    } else if (b < 9856) {
        int rem = b - 9472;
        int z = rem >> 7, sub = rem & 127;
        const float* W = z == 0 ? a2 : z == 1 ? w2 : v2;
        int kmax = (z == 2) ? 64 : 96;
        conv_tile2(W, upbuf + (size_t)z * USLOT_H, 128, HID, sub & 63, sub >> 6, tile, kmax);
    } else {
        // zero-init S_R, S_K, S_V (3*NTOK_EL floats) for split-K atomics
        int rem = b - 9856;                 // 0..1535
        float4 z4 = make_float4(0.f, 0.f, 0.f, 0.f);
#pragma unroll
        for (int j = 0; j < 4; j++) {
            size_t i = (size_t)rem * 4096 + j * 1024 + threadIdx.x * 4;
            *(float4*)(zbuf + i) = z4;
        }
    }
}

// ---------------- prep2: kk/k2 + pair scalars + pscan2 packing ----------------
__global__ void __launch_bounds__(256) prep2_kernel(
    const float* __restrict__ k, const float* __restrict__ a,
    const float* __restrict__ w, const float* __restrict__ v,
    const float* __restrict__ r,
    const float* __restrict__ k_k, const float* __restrict__ k_a,
    float* __restrict__ k2out, float* __restrict__ pscan2)
{
    int gw = (blockIdx.x * 256 + threadIdx.x) >> 5;
    int lane = threadIdx.x & 31;
    if (gw >= NPAIR * NHEAD) return;
    int pr = gw >> 5, h = gw & 31;
    int b0 = (2 * pr) * HID + h * HEADD;
    int b1 = b0 + HID;
    int cb = h * HEADD;

    float kA0 = k[b0 + lane], kB0 = k[b0 + lane + 32];
    float qA0 = kA0 * k_k[cb + lane], qB0 = kB0 * k_k[cb + lane + 32];
    float inv0 = 1.f / fmaxf(sqrtf(warp_sum(qA0 * qA0 + qB0 * qB0)), 1e-12f);
    float kkA0 = qA0 * inv0, kkB0 = qB0 * inv0;
    float aA0 = a[b0 + lane], aB0 = a[b0 + lane + 32];
    float k2A0 = kA0 * (1.f + (aA0 - 1.f) * k_a[cb + lane]);
    float k2B0 = kB0 * (1.f + (aB0 - 1.f) * k_a[cb + lane + 32]);
    k2out[b0 + lane] = k2A0;
    k2out[b0 + lane + 32] = k2B0;

    float kA1 = k[b1 + lane], kB1 = k[b1 + lane + 32];
    float qA1 = kA1 * k_k[cb + lane], qB1 = kB1 * k_k[cb + lane + 32];
    float inv1 = 1.f / fmaxf(sqrtf(warp_sum(qA1 * qA1 + qB1 * qB1)), 1e-12f);
    float kkA1 = qA1 * inv1, kkB1 = qB1 * inv1;
    float aA1 = a[b1 + lane], aB1 = a[b1 + lane + 32];
    float k2A1 = kA1 * (1.f + (aA1 - 1.f) * k_a[cb + lane]);
    float k2B1 = kB1 * (1.f + (aB1 - 1.f) * k_a[cb + lane + 32]);
    k2out[b1 + lane] = k2A1;
    k2out[b1 + lane + 32] = k2B1;

    float wA0 = w[b0 + lane], wB0 = w[b0 + lane + 32];
    float kaA0 = kkA0 * aA0, kaB0 = kkB0 * aB0;

    float c1 = warp_sum(kkA1 * kaA0 + kkB1 * kaB0);
    float c2 = warp_sum(kkA1 * k2A0 + kkB1 * k2B0);

    float* P = pscan2 + ((size_t)pr * NHEAD + h) * 1024;
    P[0 * 64 + lane] = kkA0;           P[0 * 64 + lane + 32] = kkB0;
    P[1 * 64 + lane] = kkA1 * wA0;     P[1 * 64 + lane + 32] = kkB1 * wB0;
    P[2 * 64 + lane] = wA0;            P[2 * 64 + lane + 32] = wB0;
    P[3 * 64 + lane] = kaA0;           P[3 * 64 + lane + 32] = kaB0;
    P[4 * 64 + lane] = k2A0;           P[4 * 64 + lane + 32] = k2B0;
    P[5 * 64 + lane] = r[b0 + lane];   P[5 * 64 + lane + 32] = r[b0 + lane + 32];
    P[6 * 64 + lane] = w[b1 + lane];   P[6 * 64 + lane + 32] = w[b1 + lane + 32];
    P[7 * 64 + lane] = kkA1 * aA1;     P[7 * 64 + lane + 32] = kkB1 * aB1;
    P[8 * 64 + lane] = k2A1;           P[8 * 64 + lane + 32] = k2B1;
    P[9 * 64 + lane] = r[b1 + lane];   P[9 * 64 + lane + 32] = r[b1 + lane + 32];
    P[10 * 64 + lane] = v[b0 + lane];  P[10 * 64 + lane + 32] = v[b0 + lane + 32];
    P[11 * 64 + lane] = v[b1 + lane];  P[11 * 64 + lane + 32] = v[b1 + lane + 32];
    if (lane == 0) { P[12 * 64] = c1; P[12 * 64 + 1] = c2; }
}

// ---------------- scan v3.1: two steps per round, full y reduction in-scan ----------------
__global__ void __launch_bounds__(256) scan3_kernel(
    const float* __restrict__ pscan2,
    const float* __restrict__ state2, float* __restrict__ ybuf,
    float* __restrict__ Sout)
{
    int h = blockIdx.x >> 2;
    int q = blockIdx.x & 3;
    int tid = threadIdx.x;
    int wrp = tid >> 5, lane = tid & 31;
    int rsel = lane >> 4, colg = lane & 15;
    int row = q * 16 + 2 * wrp + rsel;

    float4 S = *(const float4*)(state2 + (size_t)h * 4096 + row * 64 + colg * 4);

    __shared__ float buf[2][1024];

    const float* pB = pscan2 + (size_t)h * 1024;
    const size_t pstride = (size_t)NHEAD * 1024;

    ((float4*)buf[0])[tid] = *(const float4*)(pB + tid * 4);
    float4 preA = *(const float4*)(pB + pstride + tid * 4);
    float4 preB;

    for (int pr = 0; pr < NPAIR; pr++) {
        __syncthreads();
        preB = (pr + 2 < NPAIR) ? *(const float4*)(pB + (size_t)(pr + 2) * pstride + tid * 4)
                                : preA;
        const float* b = buf[pr & 1];
        float4 kk4  = *(const float4*)(b + 0 * 64 + colg * 4);
        float4 kkw4 = *(const float4*)(b + 1 * 64 + colg * 4);
        float4 w4   = *(const float4*)(b + 2 * 64 + colg * 4);
        float4 ka4  = *(const float4*)(b + 3 * 64 + colg * 4);
        float4 k4   = *(const float4*)(b + 4 * 64 + colg * 4);
        float4 r4   = *(const float4*)(b + 5 * 64 + colg * 4);
        float4 w14  = *(const float4*)(b + 6 * 64 + colg * 4);
        float4 ka14 = *(const float4*)(b + 7 * 64 + colg * 4);
        float4 k14  = *(const float4*)(b + 8 * 64 + colg * 4);
        float4 r14  = *(const float4*)(b + 9 * 64 + colg * 4);
        float v0 = b[10 * 64 + row];
        float v1 = b[11 * 64 + row];
        float c1 = b[12 * 64];
        float c2 = b[12 * 64 + 1];

        float d0 = S.x * kk4.x + S.y * kk4.y + S.z * kk4.z + S.w * kk4.w;
        float d1 = S.x * kkw4.x + S.y * kkw4.y + S.z * kkw4.z + S.w * kkw4.w;
#pragma unroll
        for (int o = 1; o <= 8; o <<= 1) {
            d0 += __shfl_xor_sync(0xffffffffu, d0, o);
            d1 += __shfl_xor_sync(0xffffffffu, d1, o);
        }
        float p0 = d0;
        float p1 = d1 - p0 * c1 + v0 * c2;

        S.x = S.x * w4.x - p0 * ka4.x + v0 * k4.x;
        S.y = S.y * w4.y - p0 * ka4.y + v0 * k4.y;
        S.z = S.z * w4.z - p0 * ka4.z + v0 * k4.z;
        S.w = S.w * w4.w - p0 * ka4.w + v0 * k4.w;

        float y0 = S.x * r4.x + S.y * r4.y + S.z * r4.z + S.w * r4.w;
        y0 += __shfl_xor_sync(0xffffffffu, y0, 1);
        y0 += __shfl_xor_sync(0xffffffffu, y0, 2);
        y0 += __shfl_xor_sync(0xffffffffu, y0, 4);
        y0 += __shfl_xor_sync(0xffffffffu, y0, 8);
        if (colg == 0)
            ybuf[(size_t)(2 * pr) * HID + h * HEADD + row] = y0;

        if (pr + 1 < NPAIR)
            ((float4*)buf[(pr + 1) & 1])[tid] = preA;
        preA = preB;

        S.x = S.x * w14.x - p1 * ka14.x + v1 * k14.x;
        S.y = S.y * w14.y - p1 * ka14.y + v1 * k14.y;
        S.z = S.z * w14.z - p1 * ka14.z + v1 * k14.z;
        S.w = S.w * w14.w - p1 * ka14.w + v1 * k14.w;

        float y1 = S.x * r14.x + S.y * r14.y + S.z * r14.z + S.w * r14.w;
        y1 += __shfl_xor_sync(0xffffffffu, y1, 1);
        y1 += __shfl_xor_sync(0xffffffffu, y1, 2);
        y1 += __shfl_xor_sync(0xffffffffu, y1, 4);
        y1 += __shfl_xor_sync(0xffffffffu, y1, 8);
        if (colg == 0)
            ybuf[(size_t)(2 * pr + 1) * HID + h * HEADD + row] = y1;
    }
    *(float4*)(Sout + (size_t)h * 4096 + row * 64 + colg * 4) = S;
}

// ---------------- groupnorm + rkv + gate -> single-plane fp16 into abuf ----------------
__global__ void __launch_bounds__(256) post_kernel(
    const float* __restrict__ y, const float* __restrict__ r,
    const float* __restrict__ k2, const float* __restrict__ v,
    const float* __restrict__ g, const float* __restrict__ r_k,
    const float* __restrict__ lnxw, const float* __restrict__ lnxb,
    __half* __restrict__ zsplit)
{
    int gw = (blockIdx.x * 256 + threadIdx.x) >> 5;
    int lane = threadIdx.x & 31;
    if (gw >= T_LEN * NHEAD) return;
    int t = gw >> 5, h = gw & 31;
    int base = t * HID + h * HEADD;
    int cb = h * HEADD;

    float y0 = y[base + lane], y1 = y[base + lane + 32];

    float mu = warp_sum(y0 + y1) * (1.f / HEADD);
    float d0 = y0 - mu, d1 = y1 - mu;
    float var = warp_sum(d0 * d0 + d1 * d1) * (1.f / HEADD);
    float inv = rsqrtf(var + 0.00064f);

    float rs = warp_sum(r[base + lane] * k2[base + lane] * r_k[cb + lane] +
                        r[base + lane + 32] * k2[base + lane + 32] * r_k[cb + lane + 32]);

    float z0 = (d0 * inv * lnxw[cb + lane] + lnxb[cb + lane] + rs * v[base + lane]) * g[base + lane];
    float z1 = (d1 * inv * lnxw[cb + lane + 32] + lnxb[cb + lane + 32] + rs * v[base + lane + 32]) * g[base + lane + 32];

    size_t zb = (size_t)t * 2 * HID;
    zsplit[zb + cb + lane] = __float2half_rn(z0);
    zsplit[zb + cb + lane + 32] = __float2half_rn(z1);
}

// ---------------- host launcher ----------------
extern "C" void kernel_launch(void* const* d_in, const int* in_sizes, int n_in,
                              void* d_out, int out_size)
{
    const float* x       = (const float*)d_in[0];
    const float* state1  = (const float*)d_in[1];
    const float* state2  = (const float*)d_in[2];
    const float* v_first = (const float*)d_in[3];
    const float* ln1_w   = (const float*)d_in[4];
    const float* ln1_b   = (const float*)d_in[5];
    const float* x_r     = (const float*)d_in[6];
    const float* x_w     = (const float*)d_in[7];
    const float* x_k     = (const float*)d_in[8];
    const float* x_v     = (const float*)d_in[9];
    const float* x_a     = (const float*)d_in[10];
    const float* x_g     = (const float*)d_in[11];
    const float* Wr      = (const float*)d_in[12];
    const float* Wk      = (const float*)d_in[13];
    const float* Wv      = (const float*)d_in[14];
    const float* Wo      = (const float*)d_in[15];
    const float* w0      = (const float*)d_in[16];
    const float* w1      = (const float*)d_in[17];
    const float* w2      = (const float*)d_in[18];
    const float* a0      = (const float*)d_in[19];
    const float* a1      = (const float*)d_in[20];
    const float* a2      = (const float*)d_in[21];
    const float* v0      = (const float*)d_in[22];
    const float* v1      = (const float*)d_in[23];
    const float* v2      = (const float*)d_in[24];
    const float* g1      = (const float*)d_in[25];
    const float* g2      = (const float*)d_in[26];
    const float* k_k     = (const float*)d_in[27];
    const float* k_a     = (const float*)d_in[28];
    const float* r_k     = (const float*)d_in[29];
    const float* ln_x_w  = (const float*)d_in[30];
    const float* ln_x_b  = (const float*)d_in[31];

    float* sc = nullptr;      cudaGetSymbolAddress((void**)&sc, g_scratch);
    float* pscan2 = nullptr;  cudaGetSymbolAddress((void**)&pscan2, g_pscan2);
    float* ybuf = nullptr;    cudaGetSymbolAddress((void**)&ybuf, g_y);
    __half* abuf = nullptr;   cudaGetSymbolAddress((void**)&abuf, g_abuf);
    __half* wbuf = nullptr;   cudaGetSymbolAddress((void**)&wbuf, g_wbuf);
    __half* g1buf = nullptr;  cudaGetSymbolAddress((void**)&g1buf, g_g1buf);
    __half* g2buf = nullptr;  cudaGetSymbolAddress((void**)&g2buf, g_g2buf);
    __half* ghbuf = nullptr;  cudaGetSymbolAddress((void**)&ghbuf, g_ghbuf);
    __half* lorabuf = nullptr; cudaGetSymbolAddress((void**)&lorabuf, g_lorabuf);
    __half* upbuf = nullptr;  cudaGetSymbolAddress((void**)&upbuf, g_upbuf);
    __half* hbuf_h = nullptr; cudaGetSymbolAddress((void**)&hbuf_h, g_hbuf_h);

    cudaFuncSetAttribute(mm128_kernel, cudaFuncAttributeMaxDynamicSharedMemorySize, MM_SMEM);
    cudaFuncSetAttribute(mm64_kernel, cudaFuncAttributeMaxDynamicSharedMemorySize, MM64_SMEM);

#define SLOT(s) (sc + (size_t)(s) * NTOK_EL)

    float* out = (float*)d_out;
    const int OFF_OUT = 0;
    const int OFF_S1  = NTOK_EL;
    const int OFF_S2  = OFF_S1 + HID;
    const int OFF_VF  = OFF_S2 + NHEAD * HEADD * HEADD;
    const int TOTAL   = OFF_VF + NTOK_EL;
    bool full = (out_size >= TOTAL);

    float* s1_out = full ? out + OFF_S1 : nullptr;
    float* s2_out = full ? out + OFF_S2 : SLOT(S_TMP);
    float* vf_out = full ? out + OFF_VF : nullptr;

    // 1. front: ln_mix + weight conversions + v_first copy + zero-init of S_R/S_K/S_V
    front_kernel<<<FRONT_BLOCKS, 256>>>(x, state1, ln1_w, ln1_b,
                                        x_r, x_k, x_v, x_g, x_a, x_w,
                                        abuf, s1_out,
                                        Wr, Wk, Wv, Wo, g1, g2, a1, w1, v1, v_first,
                                        a2, w2, v2,
                                        wbuf, g1buf, g2buf, lorabuf, upbuf, vf_out,
                                        SLOT(S_R));

    // 2. mega-batch (mm128): downs first (z0-3, full-K stragglers), then r/k/v split-K halves
    {
        MMJobs jobs;
        jobs.j[0] = { abuf + 3*ASLOT_H, g1buf,               (float*)ghbuf,          nullptr, nullptr, 256, HID, 2*HID, 256, 4, 1, 0,    64 };
        jobs.j[1] = { abuf + 4*ASLOT_H, lorabuf,             (float*)hbuf_h,         nullptr, nullptr, 128, HID, 2*HID, 384, 5, 1, 0,    64 };
        jobs.j[2] = { abuf + 5*ASLOT_H, lorabuf + LSLOT_H,   (float*)(hbuf_h + 128), nullptr, nullptr, 128, HID, 2*HID, 384, 6, 1, 0,    64 };
        jobs.j[3] = { abuf + 2*ASLOT_H, lorabuf + 2*LSLOT_H, (float*)(hbuf_h + 256), nullptr, nullptr, 128, HID, 2*HID, 384, 5, 1, 0,    64 };
        jobs.j[4] = { abuf,             wbuf,                SLOT(S_R), nullptr, nullptr, HID, HID, 2*HID, HID, 10, 1, 0,    32 };
        jobs.j[5] = { abuf,             wbuf,                SLOT(S_R), nullptr, nullptr, HID, HID, 2*HID, HID, 10, 1, 1024, 32 };
        jobs.j[6] = { abuf + ASLOT_H,   wbuf + WSLOT_H,      SLOT(S_K), nullptr, nullptr, HID, HID, 2*HID, HID, 10, 1, 0,    32 };
        jobs.j[7] = { abuf + ASLOT_H,   wbuf + WSLOT_H,      SLOT(S_K), nullptr, nullptr, HID, HID, 2*HID, HID, 10, 1, 1024, 32 };
        jobs.j[8] = { abuf + 2*ASLOT_H, wbuf + 2*WSLOT_H,    SLOT(S_V), nullptr, nullptr, HID, HID, 2*HID, HID, 10, 1, 0,    32 };
        jobs.j[9] = { abuf + 2*ASLOT_H, wbuf + 2*WSLOT_H,    SLOT(S_V), nullptr, nullptr, HID, HID, 2*HID, HID, 10, 1, 1024, 32 };
        mm128_kernel<<<dim3(16, 8, 10), 256, MM_SMEM>>>(jobs);
    }

    // 3. batch2: g-up + a-up + w-up + v-up (fused activations)
    {
        MMJobs jobs;
        jobs.j[0] = { ghbuf,        g2buf,             SLOT(S_G), nullptr, nullptr, HID, 256, 256, HID, 0, 1, 0, 8 };
        jobs.j[1] = { hbuf_h,       upbuf,             SLOT(S_A), nullptr, a0,      HID, 128, 384, HID, 7, 1, 0, 4 };
        jobs.j[2] = { hbuf_h + 128, upbuf + USLOT_H,   SLOT(S_W), nullptr, w0,      HID, 128, 384, HID, 8, 1, 0, 4 };
        jobs.j[3] = { hbuf_h + 256, upbuf + 2*USLOT_H, SLOT(S_V), v_first, v0,      HID, 128, 384, HID, 9, 1, 0, 4 };
        mm128_kernel<<<dim3(16, 8, 4), 256, MM_SMEM>>>(jobs);
    }

    // 4. prep pairs
    prep2_kernel<<<(NPAIR * NHEAD * 32 + 255) / 256, 256>>>(
        SLOT(S_K), SLOT(S_A), SLOT(S_W), SLOT(S_V), SLOT(S_R),
        k_k, k_a, SLOT(S_K2), pscan2);

    // 5. two-step scan (full y reduction in-scan)
    scan3_kernel<<<128, 256>>>(pscan2, state2, ybuf, s2_out);

    // 6. groupnorm + rkv + gate -> single-plane fp16 into abuf slot 0
    post_kernel<<<(T_LEN * NHEAD * 32 + 255) / 256, 256>>>(
        ybuf, SLOT(S_R), SLOT(S_K2), SLOT(S_V), SLOT(S_G),
        r_k, ln_x_w, ln_x_b, abuf);

    // 7. out = x + z@Wo (single-plane, residual fused) — mm64, 1 wave
    {
        MMJobs jobs;
        jobs.j[0] = { abuf, wbuf + 3*WSLOT_H, out + OFF_OUT, x, nullptr, HID, HID, 2*HID, HID, 1, 1, 0, 64 };
        for (int i = 1; i < 10; i++) jobs.j[i] = jobs.j[0];
        mm64_kernel<<<dim3(16, 16, 1), 256, MM64_SMEM>>>(jobs);
    }
}